// round 12
// baseline (speedup 1.0000x reference)
#include <cuda_runtime.h>
#include <cuda_fp16.h>
#include <stdint.h>

#define BB    128
#define TT    512
#define HH    256
#define LL    6
#define INW   128
#define FOURH 1024
#define NC    16
#define GRIDB (LL*NC)      // 96
#define NTH   256
#define KMAX  512
#define SIWC  (KMAX + 8)   // 520 halfs row stride (weights AND A tile)
#define GSTR  144          // per-thread gbuf slot stride in BYTES (16B-aligned)
// ws 64*520*2 + A 128*520*2 + gbuf 128*144 = 218112
#define SMEM_BYTES (64*SIWC*2 + 128*SIWC*2 + 128*GSTR)

// ---------------- persistent device state ----------------
__device__ __align__(256) __half d_wpack[(size_t)LL*FOURH*KMAX];  // rows: [Whh(256) | Wih(din)]
__device__ __align__(256) float  d_bpack[LL*FOURH];
__device__ __align__(256) __half d_xh[(size_t)BB*TT*INW];
__device__ __align__(256) __half d_hring[LL*4*BB*HH];             // 4-slot h ring per layer
__device__ unsigned g_arr2[LL*NC];   // per-CTA completed-steps counter (single writer)

__device__ __forceinline__ int hring_off(int l, int slot, int b, int k){
  return ((l*4 + slot)*BB + b)*HH + k;
}

// ---------------- prep kernels ----------------
__global__ void prep_pack(const float* __restrict__ w_ih0,
                          const float* __restrict__ w_ih,
                          const float* __restrict__ w_hh,
                          const float* __restrict__ b_ih,
                          const float* __restrict__ b_hh){
  long long idx = (long long)blockIdx.x*blockDim.x + threadIdx.x;
  if (idx >= (long long)LL*FOURH*KMAX) return;
  int k = (int)(idx % KMAX);
  int p = (int)((idx / KMAX) % FOURH);
  int l = (int)(idx / ((long long)KMAX*FOURH));
  int cid = p >> 6, rr = p & 63, gate = rr >> 4, jj = rr & 15;
  int srow = gate*HH + cid*16 + jj;
  int din  = (l == 0) ? INW : HH;
  float v = 0.f;
  if (k < HH)             v = w_hh[((size_t)l*FOURH + srow)*HH + k];
  else if (k < HH + din)  v = (l == 0) ? w_ih0[srow*INW + (k - HH)]
                                       : w_ih[((size_t)(l-1)*FOURH + srow)*HH + (k - HH)];
  d_wpack[idx] = __float2half(v);
  if (k == 0) d_bpack[l*FOURH + p] = b_ih[l*FOURH + srow] + b_hh[l*FOURH + srow];
}

__global__ void prep_x(const float* __restrict__ x){
  long long i = (long long)blockIdx.x*blockDim.x + threadIdx.x;
  if (i < (long long)BB*TT*INW) d_xh[i] = __float2half(x[i]);
}

__global__ void prep_init(const float* __restrict__ h0){
  int i = blockIdx.x*blockDim.x + threadIdx.x;
  if (i < LL*BB*HH){
    int l = i/(BB*HH), rem = i%(BB*HH);
    d_hring[hring_off(l, 0, rem/HH, rem%HH)] = __float2half(h0[i]);
  }
  if (i < LL*NC) g_arr2[i] = 0u;
}

// ---------------- low-level helpers ----------------
__device__ __forceinline__ unsigned smem_u32(const void* p){
  unsigned a;
  asm("{ .reg .u64 t; cvta.to.shared.u64 t, %1; cvt.u32.u64 %0, t; }" : "=r"(a) : "l"(p));
  return a;
}
__device__ __forceinline__ void cp_async16(uint32_t dst, const void* src){
  asm volatile("cp.async.cg.shared.global [%0], [%1], 16;" :: "r"(dst), "l"(src));
}
__device__ __forceinline__ void bar_sync(int id, int cnt){
  asm volatile("bar.sync %0, %1;" :: "r"(id), "r"(cnt) : "memory");
}
__device__ __forceinline__ void bar_arrive(int id, int cnt){
  asm volatile("bar.arrive %0, %1;" :: "r"(id), "r"(cnt) : "memory");
}
__device__ __forceinline__ void ldsm_x4(unsigned addr, unsigned& r0, unsigned& r1,
                                        unsigned& r2, unsigned& r3){
  asm volatile("ldmatrix.sync.aligned.m8n8.x4.shared.b16 {%0,%1,%2,%3}, [%4];\n"
               : "=r"(r0), "=r"(r1), "=r"(r2), "=r"(r3) : "r"(addr));
}
__device__ __forceinline__ void mma_16816(float d[4], const unsigned a[4], const unsigned b0,
                                          const unsigned b1){
  asm volatile("mma.sync.aligned.m16n8k16.row.col.f32.f16.f16.f32 "
               "{%0,%1,%2,%3}, {%4,%5,%6,%7}, {%8,%9}, {%0,%1,%2,%3};\n"
               : "+f"(d[0]), "+f"(d[1]), "+f"(d[2]), "+f"(d[3])
               : "r"(a[0]), "r"(a[1]), "r"(a[2]), "r"(a[3]), "r"(b0), "r"(b1));
}
__device__ __forceinline__ float tanh_fast(float x){
  float r; asm("tanh.approx.f32 %0, %1;" : "=f"(r) : "f"(x)); return r;
}
__device__ __forceinline__ float sig_fast(float x){
  return fmaf(tanh_fast(0.5f*x), 0.5f, 0.5f);
}
__device__ __forceinline__ void wait_ge(unsigned* p, unsigned target){
  unsigned v;
  #pragma unroll 1
  do {
    asm volatile("ld.acquire.gpu.global.u32 %0, [%1];" : "=r"(v) : "l"(p) : "memory");
  } while (v < target);
}
__device__ __forceinline__ void st_release(unsigned* p, unsigned v){
  asm volatile("st.release.gpu.global.u32 [%0], %1;" :: "l"(p), "r"(v) : "memory");
}
__device__ __forceinline__ void st_cg_u32(void* p, unsigned v){
  asm volatile("st.global.cg.u32 [%0], %1;" :: "l"(p), "r"(v) : "memory");
}
__device__ __forceinline__ void sts128(uint32_t addr, unsigned a, unsigned b,
                                       unsigned c, unsigned d){
  asm volatile("st.shared.v4.b32 [%0], {%1,%2,%3,%4};"
               :: "r"(addr), "r"(a), "r"(b), "r"(c), "r"(d) : "memory");
}
__device__ __forceinline__ void lds128(uint32_t addr, unsigned& a, unsigned& b,
                                       unsigned& c, unsigned& d){
  asm volatile("ld.shared.v4.b32 {%0,%1,%2,%3}, [%4];"
               : "=r"(a), "=r"(b), "=r"(c), "=r"(d) : "r"(addr));
}
__device__ __forceinline__ unsigned pack2(float a, float b){
  __half2 h = __floats2half2_rn(a, b);
  return *(unsigned*)&h;
}

// ---------------- per-layer persistent worker ----------------
// R10 structure (INP fully decoupled, REC owns epilogue) with:
//  - per-peer progress counters: each REC warp waits+stages its own 4 peers'
//    16-col blocks; staging overlaps peer skew
//  - single unbroken 16-iter GEMM
//  - epilogue gbuf read split into two halves (register relief)
template<int DINA>
__device__ __forceinline__ void run_layer(const int l, const int cid,
                                          const float* __restrict__ c0,
                                          float* __restrict__ out, char* smem_raw)
{
  constexpr int SIW = SIWC;
  constexpr int NI  = DINA/16;
  __half* ws = (__half*)smem_raw;            // [64][520]
  __half* A  = ws + 64*SIW;                  // [128][520]
  uint32_t* gbuf = (uint32_t*)(A + 128*SIW); // 128 slots * GSTR bytes
  const int tid = threadIdx.x;

  {
    const __half* src = d_wpack + ((size_t)(l*FOURH + cid*64))*KMAX;
    for (int v = tid; v < 64*64; v += NTH){
      int r = v >> 6, kk = (v & 63)*8;
      *(uint4*)(ws + r*SIW + kk) = *(const uint4*)(src + (size_t)r*KMAX + kk);
    }
  }

  const int w = tid >> 5, lane = tid & 31;
  const int q = lane >> 3, rs = lane & 7;
  const int gid = lane >> 2, ct = lane & 3;

  unsigned bX[4];
  {
    const int Xs[4] = {0, 8, 32, 40};
    #pragma unroll
    for (int i = 0; i < 4; i++)
      bX[i] = smem_u32(ws + (Xs[i] + rs + ((q>>1)<<4))*SIW + ((q&1)<<3));
  }
  const uint32_t Abase = smem_u32(A);

  __syncthreads();

  if (w < 4){
    // ========== REC: critical path + full epilogue ==========
    const unsigned aB0 = smem_u32(A + (w*32 + rs + ((q&1)<<3))*SIW + ((q>>1)<<3));
    const unsigned aB1 = aB0 + (unsigned)(32*SIW);
    const uint32_t gsrc = smem_u32(gbuf) + (unsigned)tid*GSTR;

    float bias[16];
    #pragma unroll
    for (int g = 0; g < 4; g++)
      #pragma unroll
      for (int jh = 0; jh < 2; jh++)
        #pragma unroll
        for (int cc = 0; cc < 2; cc++)
          bias[g*4 + jh*2 + cc] = d_bpack[l*FOURH + cid*64 + g*16 + jh*8 + ct*2 + cc];

    float creg[16];
    #pragma unroll
    for (int mt = 0; mt < 2; mt++)
      #pragma unroll
      for (int rr = 0; rr < 2; rr++)
        #pragma unroll
        for (int jh = 0; jh < 2; jh++)
          #pragma unroll
          for (int cc = 0; cc < 2; cc++){
            int row = w*32 + mt*16 + gid + rr*8;
            int col = cid*16 + jh*8 + ct*2 + cc;
            creg[mt*8 + rr*4 + jh*2 + cc] = c0[(l*BB + row)*HH + col];
          }

    for (int t = 0; t < TT; t++){
      // WAR ring check (distributed over warp-0 lanes)
      if (w == 0 && lane < NC && l < LL-1 && t >= 3)
        wait_ge(&g_arr2[(l+1)*NC + lane], (unsigned)(t-2));

      // per-peer wait + stage: warp w handles peers 4w..4w+3 (16 cols each)
      #pragma unroll
      for (int pp = 0; pp < 4; pp++){
        const int p = w*4 + pp;
        if (lane == 0 && t > 0) wait_ge(&g_arr2[l*NC + p], (unsigned)t);
        __syncwarp();
        const __half* hs = d_hring + hring_off(l, t&3, 0, p*16);
        #pragma unroll
        for (int v = lane; v < 256; v += 32){
          int r = v >> 1, kk = (v & 1)*8;
          cp_async16(Abase + (uint32_t)(r*SIW + p*16 + kk)*2u, hs + r*HH + kk);
        }
        asm volatile("cp.async.commit_group;");
      }
      asm volatile("cp.async.wait_group 0;" ::: "memory");
      bar_sync(5, 128);

      // unbroken recurrent GEMM K=256
      float acc[2][8][4];
      #pragma unroll
      for (int i = 0; i < 2; i++)
        #pragma unroll
        for (int j = 0; j < 8; j++)
          #pragma unroll
          for (int e = 0; e < 4; e++) acc[i][j][e] = 0.f;

      #pragma unroll
      for (int ki = 0; ki < 16; ki++){
        const unsigned kofs = (unsigned)(ki*32);
        unsigned a0[4], a1[4], b0[4], b1[4], b2[4], b3[4];
        ldsm_x4(aB0 + kofs, a0[0], a0[1], a0[2], a0[3]);
        ldsm_x4(aB1 + kofs, a1[0], a1[1], a1[2], a1[3]);
        ldsm_x4(bX[0] + kofs, b0[0], b0[1], b0[2], b0[3]);
        ldsm_x4(bX[1] + kofs, b1[0], b1[1], b1[2], b1[3]);
        ldsm_x4(bX[2] + kofs, b2[0], b2[1], b2[2], b2[3]);
        ldsm_x4(bX[3] + kofs, b3[0], b3[1], b3[2], b3[3]);
        #pragma unroll
        for (int mt = 0; mt < 2; mt++){
          const unsigned* a = mt ? a1 : a0;
          mma_16816(acc[mt][0], a, b0[0], b0[1]);
          mma_16816(acc[mt][1], a, b1[0], b1[1]);
          mma_16816(acc[mt][2], a, b0[2], b0[3]);
          mma_16816(acc[mt][3], a, b1[2], b1[3]);
          mma_16816(acc[mt][4], a, b2[0], b2[1]);
          mma_16816(acc[mt][5], a, b3[0], b3[1]);
          mma_16816(acc[mt][6], a, b2[2], b2[3]);
          mma_16816(acc[mt][7], a, b3[2], b3[3]);
        }
      }

      // consume INP dump (posted during our GEMM); split into halves
      bar_sync(1, NTH);
      __half* hslot = d_hring + hring_off(l, (t+1)&3, 0, 0);
      #pragma unroll
      for (int mt = 0; mt < 2; mt++){
        unsigned g16[16];
        #pragma unroll
        for (int i = 0; i < 4; i++)
          lds128(gsrc + (unsigned)((mt*4 + i)*16),
                 g16[4*i], g16[4*i+1], g16[4*i+2], g16[4*i+3]);
        if (mt == 1) bar_arrive(2, NTH);       // all gbuf reads done

        #pragma unroll
        for (int rr = 0; rr < 2; rr++){
          int row = w*32 + mt*16 + gid + rr*8;
          #pragma unroll
          for (int jh = 0; jh < 2; jh++){
            float2 dI = __half22float2(*(const __half2*)&g16[(    jh)*2 + rr]);
            float2 dF = __half22float2(*(const __half2*)&g16[(2 + jh)*2 + rr]);
            float2 dG = __half22float2(*(const __half2*)&g16[(4 + jh)*2 + rr]);
            float2 dO = __half22float2(*(const __half2*)&g16[(6 + jh)*2 + rr]);
            float hv[2];
            #pragma unroll
            for (int cc = 0; cc < 2; cc++){
              int e  = rr*2 + cc;
              int ci = mt*8 + rr*4 + jh*2 + cc;
              float gi = acc[mt][     jh][e] + (cc ? dI.y : dI.x) + bias[     jh*2 + cc];
              float gf = acc[mt][2 + jh][e] + (cc ? dF.y : dF.x) + bias[ 4 + jh*2 + cc];
              float gg = acc[mt][4 + jh][e] + (cc ? dG.y : dG.x) + bias[ 8 + jh*2 + cc];
              float go = acc[mt][6 + jh][e] + (cc ? dO.y : dO.x) + bias[12 + jh*2 + cc];
              float c  = sig_fast(gf)*creg[ci] + sig_fast(gi)*tanh_fast(gg);
              creg[ci] = c;
              hv[cc]   = sig_fast(go)*tanh_fast(c);
            }
            int col0 = cid*16 + jh*8 + ct*2;
            st_cg_u32(hslot + row*HH + col0, pack2(hv[0], hv[1]));
            if (t == TT-1){
              out[(l*BB + row)*HH + col0    ] = hv[0];
              out[(l*BB + row)*HH + col0 + 1] = hv[1];
            }
          }
        }
      }
      bar_sync(4, 128);
      if (tid == 0) st_release(&g_arr2[l*NC + cid], (unsigned)(t+1));
    }
  } else {
    // ========== INP: input stage + GEMM + dump (fully decoupled) ==========
    const int wi = w - 4;
    const unsigned aI0 = smem_u32(A + (wi*32 + rs + ((q&1)<<3))*SIW + 256 + ((q>>1)<<3));
    const unsigned aI1 = aI0 + (unsigned)(32*SIW);
    unsigned bI[4];
    #pragma unroll
    for (int i = 0; i < 4; i++) bI[i] = bX[i] + 512u;
    const uint32_t gdst = smem_u32(gbuf) + (unsigned)(tid - 128)*GSTR;

    auto stage_input = [&](int tt){
      if (DINA == INW){                      // layer 0: x, no wait
        for (int v = tid - 128; v < 2048; v += 128){
          int r = v >> 4, kk = (v & 15)*8;
          cp_async16(Abase + (uint32_t)(r*SIW + 256 + kk)*2u,
                     d_xh + ((size_t)r*TT + tt)*INW + kk);
        }
        asm volatile("cp.async.commit_group;");
      } else {                               // per-peer wait + stage from below
        #pragma unroll
        for (int pp = 0; pp < 4; pp++){
          const int p = wi*4 + pp;
          if (lane == 0) wait_ge(&g_arr2[(l-1)*NC + p], (unsigned)(tt+1));
          __syncwarp();
          const __half* hb = d_hring + hring_off(l-1, (tt+1)&3, 0, p*16);
          #pragma unroll
          for (int v = lane; v < 256; v += 32){
            int r = v >> 1, kk = (v & 1)*8;
            cp_async16(Abase + (uint32_t)(r*SIW + 256 + p*16 + kk)*2u, hb + r*HH + kk);
          }
          asm volatile("cp.async.commit_group;");
        }
      }
      asm volatile("cp.async.wait_group 0;" ::: "memory");
    };

    stage_input(0);
    bar_sync(3, 128);

    for (int t = 0; t < TT; t++){
      float accI[2][8][4];
      #pragma unroll
      for (int i = 0; i < 2; i++)
        #pragma unroll
        for (int j = 0; j < 8; j++)
          #pragma unroll
          for (int e = 0; e < 4; e++) accI[i][j][e] = 0.f;

      #pragma unroll
      for (int ki = 0; ki < NI; ki++){
        const unsigned kofs = (unsigned)(ki*32);
        unsigned a0[4], a1[4], b0[4], b1[4], b2[4], b3[4];
        ldsm_x4(aI0 + kofs, a0[0], a0[1], a0[2], a0[3]);
        ldsm_x4(aI1 + kofs, a1[0], a1[1], a1[2], a1[3]);
        ldsm_x4(bI[0] + kofs, b0[0], b0[1], b0[2], b0[3]);
        ldsm_x4(bI[1] + kofs, b1[0], b1[1], b1[2], b1[3]);
        ldsm_x4(bI[2] + kofs, b2[0], b2[1], b2[2], b2[3]);
        ldsm_x4(bI[3] + kofs, b3[0], b3[1], b3[2], b3[3]);
        #pragma unroll
        for (int mt = 0; mt < 2; mt++){
          const unsigned* a = mt ? a1 : a0;
          mma_16816(accI[mt][0], a, b0[0], b0[1]);
          mma_16816(accI[mt][1], a, b1[0], b1[1]);
          mma_16816(accI[mt][2], a, b0[2], b0[3]);
          mma_16816(accI[mt][3], a, b1[2], b1[3]);
          mma_16816(accI[mt][4], a, b2[0], b2[1]);
          mma_16816(accI[mt][5], a, b3[0], b3[1]);
          mma_16816(accI[mt][6], a, b2[2], b2[3]);
          mma_16816(accI[mt][7], a, b3[2], b3[3]);
        }
      }

      if (t > 0) bar_sync(2, NTH);     // REC consumed dump(t-1)
      #pragma unroll
      for (int i = 0; i < 8; i++){
        const int j0 = 2*i, j1 = 2*i + 1;
        const float* t0 = accI[j0 >> 3][j0 & 7];
        const float* t1 = accI[j1 >> 3][j1 & 7];
        sts128(gdst + (unsigned)(i*16),
               pack2(t0[0], t0[1]), pack2(t0[2], t0[3]),
               pack2(t1[0], t1[1]), pack2(t1[2], t1[3]));
      }
      asm volatile("membar.cta;" ::: "memory");
      bar_arrive(1, NTH);              // dump(t) ready; REC consumes

      if (t < TT-1){
        bar_sync(3, 128);              // all INP warps done with GEMM(t) reads
        stage_input(t+1);
        bar_sync(3, 128);
      }
    }
  }
}

__global__ void __launch_bounds__(NTH, 1)
lstm_persist(const float* __restrict__ c0, float* __restrict__ out)
{
  extern __shared__ __align__(16) char smem_raw[];
  const int l = blockIdx.x >> 4, cid = blockIdx.x & 15;
  if (l == 0) run_layer<INW>(0, cid, c0, out, smem_raw);
  else        run_layer<HH >(l, cid, c0, out, smem_raw);
}

// ---------------- launch ----------------
extern "C" void kernel_launch(void* const* d_in, const int* in_sizes, int n_in,
                              void* d_out, int out_size){
  const float* x     = (const float*)d_in[0];
  const float* h0    = (const float*)d_in[1];
  const float* c0    = (const float*)d_in[2];
  const float* w_ih0 = (const float*)d_in[3];
  const float* w_ih  = (const float*)d_in[4];
  const float* w_hh  = (const float*)d_in[5];
  const float* b_ih  = (const float*)d_in[6];
  const float* b_hh  = (const float*)d_in[7];
  float* out = (float*)d_out;

  cudaFuncSetAttribute(lstm_persist, cudaFuncAttributeMaxDynamicSharedMemorySize, SMEM_BYTES);

  prep_pack<<<(LL*FOURH*KMAX + 255)/256, 256>>>(w_ih0, w_ih, w_hh, b_ih, b_hh);
  prep_x   <<<(BB*TT*INW    + 255)/256, 256>>>(x);
  prep_init<<<(LL*BB*HH     + 255)/256, 256>>>(h0);
  lstm_persist<<<GRIDB, NTH, SMEM_BYTES>>>(c0, out);
}

// round 13
// speedup vs baseline: 1.6525x; 1.6525x over previous
#include <cuda_runtime.h>
#include <cuda_fp16.h>
#include <stdint.h>

#define BB    128
#define TT    512
#define HH    256
#define LL    6
#define INW   128
#define FOURH 1024
#define NC    16
#define GRIDB (LL*NC)      // 96
#define NTH   256
#define KMAX  512
#define SIWC  (KMAX + 8)   // 520 halfs row stride (weights AND A tile)
#define GSTR  144          // per-thread gbuf slot stride in BYTES (16B-aligned)
// ws 64*520*2 + A 128*520*2 + gbuf 128*144 = 218112
#define SMEM_BYTES (64*SIWC*2 + 128*SIWC*2 + 128*GSTR)

// ---------------- persistent device state ----------------
__device__ __align__(256) __half d_wpack[(size_t)LL*FOURH*KMAX];  // rows: [Whh(256) | Wih(din)]
__device__ __align__(256) float  d_bpack[LL*FOURH];
__device__ __align__(256) __half d_xh[(size_t)BB*TT*INW];
__device__ __align__(256) __half d_hring[LL*4*BB*HH];             // 4-slot h ring per layer
__device__ unsigned g_arrive[LL];

__device__ __forceinline__ int hring_off(int l, int slot, int b, int k){
  return ((l*4 + slot)*BB + b)*HH + k;
}

// ---------------- prep kernels ----------------
__global__ void prep_pack(const float* __restrict__ w_ih0,
                          const float* __restrict__ w_ih,
                          const float* __restrict__ w_hh,
                          const float* __restrict__ b_ih,
                          const float* __restrict__ b_hh){
  long long idx = (long long)blockIdx.x*blockDim.x + threadIdx.x;
  if (idx >= (long long)LL*FOURH*KMAX) return;
  int k = (int)(idx % KMAX);
  int p = (int)((idx / KMAX) % FOURH);
  int l = (int)(idx / ((long long)KMAX*FOURH));
  int cid = p >> 6, rr = p & 63, gate = rr >> 4, jj = rr & 15;
  int srow = gate*HH + cid*16 + jj;
  int din  = (l == 0) ? INW : HH;
  float v = 0.f;
  if (k < HH)             v = w_hh[((size_t)l*FOURH + srow)*HH + k];
  else if (k < HH + din)  v = (l == 0) ? w_ih0[srow*INW + (k - HH)]
                                       : w_ih[((size_t)(l-1)*FOURH + srow)*HH + (k - HH)];
  d_wpack[idx] = __float2half(v);
  if (k == 0) d_bpack[l*FOURH + p] = b_ih[l*FOURH + srow] + b_hh[l*FOURH + srow];
}

__global__ void prep_x(const float* __restrict__ x){
  long long i = (long long)blockIdx.x*blockDim.x + threadIdx.x;
  if (i < (long long)BB*TT*INW) d_xh[i] = __float2half(x[i]);
}

__global__ void prep_init(const float* __restrict__ h0){
  int i = blockIdx.x*blockDim.x + threadIdx.x;
  if (i < LL*BB*HH){
    int l = i/(BB*HH), rem = i%(BB*HH);
    d_hring[hring_off(l, 0, rem/HH, rem%HH)] = __float2half(h0[i]);
  }
  if (i == 0){
    #pragma unroll
    for (int l = 0; l < LL; l++) g_arrive[l] = 0u;
  }
}

// ---------------- low-level helpers ----------------
__device__ __forceinline__ unsigned smem_u32(const void* p){
  unsigned a;
  asm("{ .reg .u64 t; cvta.to.shared.u64 t, %1; cvt.u32.u64 %0, t; }" : "=r"(a) : "l"(p));
  return a;
}
__device__ __forceinline__ void cp_async16(uint32_t dst, const void* src){
  asm volatile("cp.async.cg.shared.global [%0], [%1], 16;" :: "r"(dst), "l"(src));
}
__device__ __forceinline__ void bar_sync(int id, int cnt){
  asm volatile("bar.sync %0, %1;" :: "r"(id), "r"(cnt) : "memory");
}
__device__ __forceinline__ void bar_arrive(int id, int cnt){
  asm volatile("bar.arrive %0, %1;" :: "r"(id), "r"(cnt) : "memory");
}
__device__ __forceinline__ void ldsm_x4(unsigned addr, unsigned& r0, unsigned& r1,
                                        unsigned& r2, unsigned& r3){
  asm volatile("ldmatrix.sync.aligned.m8n8.x4.shared.b16 {%0,%1,%2,%3}, [%4];\n"
               : "=r"(r0), "=r"(r1), "=r"(r2), "=r"(r3) : "r"(addr));
}
__device__ __forceinline__ void mma_16816(float d[4], const unsigned a[4], const unsigned b0,
                                          const unsigned b1){
  asm volatile("mma.sync.aligned.m16n8k16.row.col.f32.f16.f16.f32 "
               "{%0,%1,%2,%3}, {%4,%5,%6,%7}, {%8,%9}, {%0,%1,%2,%3};\n"
               : "+f"(d[0]), "+f"(d[1]), "+f"(d[2]), "+f"(d[3])
               : "r"(a[0]), "r"(a[1]), "r"(a[2]), "r"(a[3]), "r"(b0), "r"(b1));
}
__device__ __forceinline__ float tanh_fast(float x){
  float r; asm("tanh.approx.f32 %0, %1;" : "=f"(r) : "f"(x)); return r;
}
__device__ __forceinline__ float sig_fast(float x){
  return fmaf(tanh_fast(0.5f*x), 0.5f, 0.5f);
}
__device__ __forceinline__ void wait_ge(unsigned* p, unsigned target){
  unsigned v;
  #pragma unroll 1
  do {
    asm volatile("ld.acquire.gpu.global.u32 %0, [%1];" : "=r"(v) : "l"(p) : "memory");
  } while (v < target);
}
__device__ __forceinline__ void arrive_release(unsigned* p){
  asm volatile("red.release.gpu.global.add.u32 [%0], %1;" :: "l"(p), "r"(1u) : "memory");
}
__device__ __forceinline__ void st_cg_u32(void* p, unsigned v){
  asm volatile("st.global.cg.u32 [%0], %1;" :: "l"(p), "r"(v) : "memory");
}
__device__ __forceinline__ void sts128(uint32_t addr, unsigned a, unsigned b,
                                       unsigned c, unsigned d){
  asm volatile("st.shared.v4.b32 [%0], {%1,%2,%3,%4};"
               :: "r"(addr), "r"(a), "r"(b), "r"(c), "r"(d) : "memory");
}
__device__ __forceinline__ void lds128(uint32_t addr, unsigned& a, unsigned& b,
                                       unsigned& c, unsigned& d){
  asm volatile("ld.shared.v4.b32 {%0,%1,%2,%3}, [%4];"
               : "=r"(a), "=r"(b), "=r"(c), "=r"(d) : "r"(addr));
}
__device__ __forceinline__ unsigned pack2(float a, float b){
  __half2 h = __floats2half2_rn(a, b);
  return *(unsigned*)&h;
}

// ---------------- per-layer persistent worker ----------------
// R10 structure: INP warps (4-7) stage+GEMM the input contribution and dump
// it (fp16) to gbuf DURING REC's recurrent GEMM; REC warps (0-3) consume the
// dump and run the full gate epilogue (creg lives in REC). Single aggregated
// per-layer release counter (R12's fine-grained polling regressed 2.6x).
// R13 patch: gbuf consumed in two 16-word halves to cut register pressure.
template<int DINA>
__device__ __forceinline__ void run_layer(const int l, const int cid,
                                          const float* __restrict__ c0,
                                          float* __restrict__ out, char* smem_raw)
{
  constexpr int SIW = SIWC;
  constexpr int NI  = DINA/16;               // input k16 iters
  constexpr int CHI = DINA/8;                // input 16B chunks per row
  __half* ws = (__half*)smem_raw;            // [64][520]
  __half* A  = ws + 64*SIW;                  // [128][520]
  uint32_t* gbuf = (uint32_t*)(A + 128*SIW); // 128 slots * GSTR bytes
  const int tid = threadIdx.x;

  {
    const __half* src = d_wpack + ((size_t)(l*FOURH + cid*64))*KMAX;
    for (int v = tid; v < 64*64; v += NTH){
      int r = v >> 6, kk = (v & 63)*8;
      *(uint4*)(ws + r*SIW + kk) = *(const uint4*)(src + (size_t)r*KMAX + kk);
    }
  }

  const int w = tid >> 5, lane = tid & 31;
  const int q = lane >> 3, rs = lane & 7;
  const int gid = lane >> 2, ct = lane & 3;

  unsigned bX[4];
  {
    const int Xs[4] = {0, 8, 32, 40};
    #pragma unroll
    for (int i = 0; i < 4; i++)
      bX[i] = smem_u32(ws + (Xs[i] + rs + ((q>>1)<<4))*SIW + ((q&1)<<3));
  }
  const uint32_t Abase = smem_u32(A);

  __syncthreads();

  if (w < 4){
    // ========== REC warps: critical path + epilogue ==========
    const unsigned aB0 = smem_u32(A + (w*32 + rs + ((q&1)<<3))*SIW + ((q>>1)<<3));
    const unsigned aB1 = aB0 + (unsigned)(32*SIW);
    const uint32_t gsrc = smem_u32(gbuf) + (unsigned)tid*GSTR;

    float bias[16];
    #pragma unroll
    for (int g = 0; g < 4; g++)
      #pragma unroll
      for (int jh = 0; jh < 2; jh++)
        #pragma unroll
        for (int cc = 0; cc < 2; cc++)
          bias[g*4 + jh*2 + cc] = d_bpack[l*FOURH + cid*64 + g*16 + jh*8 + ct*2 + cc];

    float creg[16];
    #pragma unroll
    for (int mt = 0; mt < 2; mt++)
      #pragma unroll
      for (int rr = 0; rr < 2; rr++)
        #pragma unroll
        for (int jh = 0; jh < 2; jh++)
          #pragma unroll
          for (int cc = 0; cc < 2; cc++){
            int row = w*32 + mt*16 + gid + rr*8;
            int col = cid*16 + jh*8 + ct*2 + cc;
            creg[mt*8 + rr*4 + jh*2 + cc] = c0[(l*BB + row)*HH + col];
          }

    for (int t = 0; t < TT; t++){
      if (tid == 0){
        if (t > 0)               wait_ge(&g_arrive[l],   16u*(unsigned)t);
        if (l < LL-1 && t >= 3)  wait_ge(&g_arrive[l+1], 16u*(unsigned)(t-2));
      }
      bar_sync(4, 128);

      // stage own h_{t-1} (slot t&3) into A cols [0,256), two K-half groups
      const __half* hs = d_hring + hring_off(l, t&3, 0, 0);
      for (int v = tid; v < 2048; v += 128){
        int r = v >> 4, c = (v & 15)*8;
        cp_async16(Abase + (uint32_t)(r*SIW + c)*2u, hs + r*HH + c);
      }
      asm volatile("cp.async.commit_group;");
      for (int v = tid; v < 2048; v += 128){
        int r = v >> 4, c = 128 + (v & 15)*8;
        cp_async16(Abase + (uint32_t)(r*SIW + c)*2u, hs + r*HH + c);
      }
      asm volatile("cp.async.commit_group;");

      float acc[2][8][4];
      #pragma unroll
      for (int i = 0; i < 2; i++)
        #pragma unroll
        for (int j = 0; j < 8; j++)
          #pragma unroll
          for (int e = 0; e < 4; e++) acc[i][j][e] = 0.f;

      asm volatile("cp.async.wait_group 1;" ::: "memory");
      bar_sync(5, 128);
      #pragma unroll
      for (int ki = 0; ki < 8; ki++){
        const unsigned kofs = (unsigned)(ki*32);
        unsigned a0[4], a1[4], b0[4], b1[4], b2[4], b3[4];
        ldsm_x4(aB0 + kofs, a0[0], a0[1], a0[2], a0[3]);
        ldsm_x4(aB1 + kofs, a1[0], a1[1], a1[2], a1[3]);
        ldsm_x4(bX[0] + kofs, b0[0], b0[1], b0[2], b0[3]);
        ldsm_x4(bX[1] + kofs, b1[0], b1[1], b1[2], b1[3]);
        ldsm_x4(bX[2] + kofs, b2[0], b2[1], b2[2], b2[3]);
        ldsm_x4(bX[3] + kofs, b3[0], b3[1], b3[2], b3[3]);
        #pragma unroll
        for (int mt = 0; mt < 2; mt++){
          const unsigned* a = mt ? a1 : a0;
          mma_16816(acc[mt][0], a, b0[0], b0[1]);
          mma_16816(acc[mt][1], a, b1[0], b1[1]);
          mma_16816(acc[mt][2], a, b0[2], b0[3]);
          mma_16816(acc[mt][3], a, b1[2], b1[3]);
          mma_16816(acc[mt][4], a, b2[0], b2[1]);
          mma_16816(acc[mt][5], a, b3[0], b3[1]);
          mma_16816(acc[mt][6], a, b2[2], b2[3]);
          mma_16816(acc[mt][7], a, b3[2], b3[3]);
        }
      }
      asm volatile("cp.async.wait_group 0;" ::: "memory");
      bar_sync(4, 128);
      #pragma unroll
      for (int ki = 8; ki < 16; ki++){
        const unsigned kofs = (unsigned)(ki*32);
        unsigned a0[4], a1[4], b0[4], b1[4], b2[4], b3[4];
        ldsm_x4(aB0 + kofs, a0[0], a0[1], a0[2], a0[3]);
        ldsm_x4(aB1 + kofs, a1[0], a1[1], a1[2], a1[3]);
        ldsm_x4(bX[0] + kofs, b0[0], b0[1], b0[2], b0[3]);
        ldsm_x4(bX[1] + kofs, b1[0], b1[1], b1[2], b1[3]);
        ldsm_x4(bX[2] + kofs, b2[0], b2[1], b2[2], b2[3]);
        ldsm_x4(bX[3] + kofs, b3[0], b3[1], b3[2], b3[3]);
        #pragma unroll
        for (int mt = 0; mt < 2; mt++){
          const unsigned* a = mt ? a1 : a0;
          mma_16816(acc[mt][0], a, b0[0], b0[1]);
          mma_16816(acc[mt][1], a, b1[0], b1[1]);
          mma_16816(acc[mt][2], a, b0[2], b0[3]);
          mma_16816(acc[mt][3], a, b1[2], b1[3]);
          mma_16816(acc[mt][4], a, b2[0], b2[1]);
          mma_16816(acc[mt][5], a, b3[0], b3[1]);
          mma_16816(acc[mt][6], a, b2[2], b2[3]);
          mma_16816(acc[mt][7], a, b3[2], b3[3]);
        }
      }

      // consume INP dump in two halves (register relief); epilogue per half
      bar_sync(1, NTH);
      __half* hslot = d_hring + hring_off(l, (t+1)&3, 0, 0);
      #pragma unroll
      for (int mt = 0; mt < 2; mt++){
        unsigned g16[16];
        #pragma unroll
        for (int i = 0; i < 4; i++)
          lds128(gsrc + (unsigned)((mt*4 + i)*16),
                 g16[4*i], g16[4*i+1], g16[4*i+2], g16[4*i+3]);
        if (mt == 1) bar_arrive(2, NTH);       // all gbuf reads complete

        #pragma unroll
        for (int rr = 0; rr < 2; rr++){
          int row = w*32 + mt*16 + gid + rr*8;
          #pragma unroll
          for (int jh = 0; jh < 2; jh++){
            float2 dI = __half22float2(*(const __half2*)&g16[(    jh)*2 + rr]);
            float2 dF = __half22float2(*(const __half2*)&g16[(2 + jh)*2 + rr]);
            float2 dG = __half22float2(*(const __half2*)&g16[(4 + jh)*2 + rr]);
            float2 dO = __half22float2(*(const __half2*)&g16[(6 + jh)*2 + rr]);
            float hv[2];
            #pragma unroll
            for (int cc = 0; cc < 2; cc++){
              int e  = rr*2 + cc;
              int ci = mt*8 + rr*4 + jh*2 + cc;
              float gi = acc[mt][     jh][e] + (cc ? dI.y : dI.x) + bias[     jh*2 + cc];
              float gf = acc[mt][2 + jh][e] + (cc ? dF.y : dF.x) + bias[ 4 + jh*2 + cc];
              float gg = acc[mt][4 + jh][e] + (cc ? dG.y : dG.x) + bias[ 8 + jh*2 + cc];
              float go = acc[mt][6 + jh][e] + (cc ? dO.y : dO.x) + bias[12 + jh*2 + cc];
              float c  = sig_fast(gf)*creg[ci] + sig_fast(gi)*tanh_fast(gg);
              creg[ci] = c;
              hv[cc]   = sig_fast(go)*tanh_fast(c);
            }
            int col0 = cid*16 + jh*8 + ct*2;
            st_cg_u32(hslot + row*HH + col0, pack2(hv[0], hv[1]));
            if (t == TT-1){
              out[(l*BB + row)*HH + col0    ] = hv[0];
              out[(l*BB + row)*HH + col0 + 1] = hv[1];
            }
          }
        }
      }
      bar_sync(4, 128);
      if (tid == 0) arrive_release(&g_arrive[l]);
    }
  } else {
    // ========== INP warps: input stage + GEMM + dump (off critical path) ==========
    const int wi = w - 4;
    const unsigned aI0 = smem_u32(A + (wi*32 + rs + ((q&1)<<3))*SIW + 256 + ((q>>1)<<3));
    const unsigned aI1 = aI0 + (unsigned)(32*SIW);
    unsigned bI[4];
    #pragma unroll
    for (int i = 0; i < 4; i++) bI[i] = bX[i] + 512u;
    const uint32_t gdst = smem_u32(gbuf) + (unsigned)(tid - 128)*GSTR;

    auto stage_input = [&](int tt){
      for (int v = tid - 128; v < 128*CHI; v += 128){
        int r = v / CHI, kk = (v - r*CHI)*8;
        const __half* src = (DINA == INW)
          ? d_xh + ((size_t)r*TT + tt)*INW + kk
          : d_hring + hring_off(l-1, (tt+1)&3, r, kk);
        cp_async16(Abase + (uint32_t)(r*SIW + 256 + kk)*2u, src);
      }
      asm volatile("cp.async.commit_group;");
      asm volatile("cp.async.wait_group 0;" ::: "memory");
    };

    if (tid == 128 && l > 0) wait_ge(&g_arrive[l-1], 16u);
    bar_sync(3, 128);
    stage_input(0);
    bar_sync(3, 128);

    for (int t = 0; t < TT; t++){
      float accI[2][8][4];
      #pragma unroll
      for (int i = 0; i < 2; i++)
        #pragma unroll
        for (int j = 0; j < 8; j++)
          #pragma unroll
          for (int e = 0; e < 4; e++) accI[i][j][e] = 0.f;
      #pragma unroll
      for (int ki = 0; ki < NI; ki++){
        const unsigned kofs = (unsigned)(ki*32);
        unsigned a0[4], a1[4], b0[4], b1[4], b2[4], b3[4];
        ldsm_x4(aI0 + kofs, a0[0], a0[1], a0[2], a0[3]);
        ldsm_x4(aI1 + kofs, a1[0], a1[1], a1[2], a1[3]);
        ldsm_x4(bI[0] + kofs, b0[0], b0[1], b0[2], b0[3]);
        ldsm_x4(bI[1] + kofs, b1[0], b1[1], b1[2], b1[3]);
        ldsm_x4(bI[2] + kofs, b2[0], b2[1], b2[2], b2[3]);
        ldsm_x4(bI[3] + kofs, b3[0], b3[1], b3[2], b3[3]);
        #pragma unroll
        for (int mt = 0; mt < 2; mt++){
          const unsigned* a = mt ? a1 : a0;
          mma_16816(accI[mt][0], a, b0[0], b0[1]);
          mma_16816(accI[mt][1], a, b1[0], b1[1]);
          mma_16816(accI[mt][2], a, b0[2], b0[3]);
          mma_16816(accI[mt][3], a, b1[2], b1[3]);
          mma_16816(accI[mt][4], a, b2[0], b2[1]);
          mma_16816(accI[mt][5], a, b3[0], b3[1]);
          mma_16816(accI[mt][6], a, b2[2], b2[3]);
          mma_16816(accI[mt][7], a, b3[2], b3[3]);
        }
      }

      if (t > 0) bar_sync(2, NTH);     // REC consumed dump(t-1)
      #pragma unroll
      for (int i = 0; i < 8; i++){
        const int j0 = 2*i, j1 = 2*i + 1;
        const float* t0 = accI[j0 >> 3][j0 & 7];
        const float* t1 = accI[j1 >> 3][j1 & 7];
        sts128(gdst + (unsigned)(i*16),
               pack2(t0[0], t0[1]), pack2(t0[2], t0[3]),
               pack2(t1[0], t1[1]), pack2(t1[2], t1[3]));
      }
      asm volatile("membar.cta;" ::: "memory");
      bar_arrive(1, NTH);              // dump(t) ready; REC consumes

      if (t < TT-1){
        if (tid == 128 && l > 0) wait_ge(&g_arrive[l-1], 16u*(unsigned)(t+2));
        bar_sync(3, 128);
        stage_input(t+1);
        bar_sync(3, 128);
      }
    }
  }
}

__global__ void __launch_bounds__(NTH, 1)
lstm_persist(const float* __restrict__ c0, float* __restrict__ out)
{
  extern __shared__ __align__(16) char smem_raw[];
  const int l = blockIdx.x >> 4, cid = blockIdx.x & 15;
  if (l == 0) run_layer<INW>(0, cid, c0, out, smem_raw);
  else        run_layer<HH >(l, cid, c0, out, smem_raw);
}

// ---------------- launch ----------------
extern "C" void kernel_launch(void* const* d_in, const int* in_sizes, int n_in,
                              void* d_out, int out_size){
  const float* x     = (const float*)d_in[0];
  const float* h0    = (const float*)d_in[1];
  const float* c0    = (const float*)d_in[2];
  const float* w_ih0 = (const float*)d_in[3];
  const float* w_ih  = (const float*)d_in[4];
  const float* w_hh  = (const float*)d_in[5];
  const float* b_ih  = (const float*)d_in[6];
  const float* b_hh  = (const float*)d_in[7];
  float* out = (float*)d_out;

  cudaFuncSetAttribute(lstm_persist, cudaFuncAttributeMaxDynamicSharedMemorySize, SMEM_BYTES);

  prep_pack<<<(LL*FOURH*KMAX + 255)/256, 256>>>(w_ih0, w_ih, w_hh, b_ih, b_hh);
  prep_x   <<<(BB*TT*INW    + 255)/256, 256>>>(x);
  prep_init<<<(LL*BB*HH     + 255)/256, 256>>>(h0);
  lstm_persist<<<GRIDB, NTH, SMEM_BYTES>>>(c0, out);
}

// round 14
// speedup vs baseline: 2.5775x; 1.5598x over previous
#include <cuda_runtime.h>
#include <cuda_fp16.h>
#include <stdint.h>

#define BB    128
#define TT    512
#define HH    256
#define LL    6
#define INW   128
#define FOURH 1024
#define NC    16
#define GRIDB (LL*NC)      // 96
#define NTH   256
#define KMAX  512
#define SIWC  (KMAX + 8)   // 520 halfs row stride (weights AND A tile)
#define GSTR  144          // per-thread gbuf slot stride in BYTES (16B-aligned)
// ws 64*520*2 + A 128*520*2 + gbuf 128*144 = 218112
#define SMEM_BYTES (64*SIWC*2 + 128*SIWC*2 + 128*GSTR)

// ---------------- persistent device state ----------------
__device__ __align__(256) __half d_wpack[(size_t)LL*FOURH*KMAX];  // rows: [Whh(256) | Wih(din)]
__device__ __align__(256) float  d_bpack[LL*FOURH];
__device__ __align__(256) __half d_xh[(size_t)BB*TT*INW];
__device__ __align__(256) __half d_hring[LL*4*BB*HH];             // 4-slot h ring per layer
__device__ unsigned g_arrive[LL];

__device__ __forceinline__ int hring_off(int l, int slot, int b, int k){
  return ((l*4 + slot)*BB + b)*HH + k;
}

// ---------------- prep kernels (vectorized: 8 halfs / thread) ----------------
__global__ void prep_pack(const float* __restrict__ w_ih0,
                          const float* __restrict__ w_ih,
                          const float* __restrict__ w_hh,
                          const float* __restrict__ b_ih,
                          const float* __restrict__ b_hh){
  int idx = blockIdx.x*blockDim.x + threadIdx.x;     // over LL*FOURH*(KMAX/8)
  if (idx >= LL*FOURH*(KMAX/8)) return;
  int kb = idx % (KMAX/8);
  int p  = (idx / (KMAX/8)) % FOURH;
  int l  =  idx / ((KMAX/8)*FOURH);
  int cid = p >> 6, rr = p & 63, gate = rr >> 4, jj = rr & 15;
  int srow = gate*HH + cid*16 + jj;
  int din  = (l == 0) ? INW : HH;
  __half hv[8];
  #pragma unroll
  for (int u = 0; u < 8; u++){
    int k = kb*8 + u;
    float v = 0.f;
    if (k < HH)             v = w_hh[((size_t)l*FOURH + srow)*HH + k];
    else if (k < HH + din)  v = (l == 0) ? w_ih0[srow*INW + (k - HH)]
                                         : w_ih[((size_t)(l-1)*FOURH + srow)*HH + (k - HH)];
    hv[u] = __float2half(v);
  }
  *(uint4*)&d_wpack[((size_t)(l*FOURH + p))*KMAX + kb*8] = *(uint4*)hv;
  if (kb == 0) d_bpack[l*FOURH + p] = b_ih[l*FOURH + srow] + b_hh[l*FOURH + srow];
}

__global__ void prep_x(const float* __restrict__ x){
  long long i = (long long)blockIdx.x*blockDim.x + threadIdx.x;  // over BB*TT*INW/8
  if (i >= (long long)BB*TT*INW/8) return;
  const float4* x4 = (const float4*)x;
  float4 a = x4[2*i], b = x4[2*i + 1];
  __half hv[8] = { __float2half(a.x), __float2half(a.y), __float2half(a.z), __float2half(a.w),
                   __float2half(b.x), __float2half(b.y), __float2half(b.z), __float2half(b.w) };
  *(uint4*)&d_xh[i*8] = *(uint4*)hv;
}

__global__ void prep_init(const float* __restrict__ h0){
  int i = blockIdx.x*blockDim.x + threadIdx.x;
  if (i < LL*BB*HH){
    int l = i/(BB*HH), rem = i%(BB*HH);
    d_hring[hring_off(l, 0, rem/HH, rem%HH)] = __float2half(h0[i]);
  }
  if (i == 0){
    #pragma unroll
    for (int l = 0; l < LL; l++) g_arrive[l] = 0u;
  }
}

// ---------------- low-level helpers ----------------
__device__ __forceinline__ unsigned smem_u32(const void* p){
  unsigned a;
  asm("{ .reg .u64 t; cvta.to.shared.u64 t, %1; cvt.u32.u64 %0, t; }" : "=r"(a) : "l"(p));
  return a;
}
__device__ __forceinline__ void cp_async16(uint32_t dst, const void* src){
  asm volatile("cp.async.cg.shared.global [%0], [%1], 16;" :: "r"(dst), "l"(src));
}
__device__ __forceinline__ void bar_sync(int id, int cnt){
  asm volatile("bar.sync %0, %1;" :: "r"(id), "r"(cnt) : "memory");
}
__device__ __forceinline__ void bar_arrive(int id, int cnt){
  asm volatile("bar.arrive %0, %1;" :: "r"(id), "r"(cnt) : "memory");
}
__device__ __forceinline__ void ldsm_x4(unsigned addr, unsigned& r0, unsigned& r1,
                                        unsigned& r2, unsigned& r3){
  asm volatile("ldmatrix.sync.aligned.m8n8.x4.shared.b16 {%0,%1,%2,%3}, [%4];\n"
               : "=r"(r0), "=r"(r1), "=r"(r2), "=r"(r3) : "r"(addr));
}
__device__ __forceinline__ void mma_16816(float d[4], const unsigned a[4], const unsigned b0,
                                          const unsigned b1){
  asm volatile("mma.sync.aligned.m16n8k16.row.col.f32.f16.f16.f32 "
               "{%0,%1,%2,%3}, {%4,%5,%6,%7}, {%8,%9}, {%0,%1,%2,%3};\n"
               : "+f"(d[0]), "+f"(d[1]), "+f"(d[2]), "+f"(d[3])
               : "r"(a[0]), "r"(a[1]), "r"(a[2]), "r"(a[3]), "r"(b0), "r"(b1));
}
__device__ __forceinline__ float tanh_fast(float x){
  float r; asm("tanh.approx.f32 %0, %1;" : "=f"(r) : "f"(x)); return r;
}
__device__ __forceinline__ float sig_fast(float x){
  return fmaf(tanh_fast(0.5f*x), 0.5f, 0.5f);
}
__device__ __forceinline__ void wait_ge(unsigned* p, unsigned target){
  unsigned v;
  #pragma unroll 1
  do {
    asm volatile("ld.acquire.gpu.global.u32 %0, [%1];" : "=r"(v) : "l"(p) : "memory");
  } while (v < target);
}
__device__ __forceinline__ void arrive_release(unsigned* p){
  asm volatile("red.release.gpu.global.add.u32 [%0], %1;" :: "l"(p), "r"(1u) : "memory");
}
__device__ __forceinline__ void st_cg_u32(void* p, unsigned v){
  asm volatile("st.global.cg.u32 [%0], %1;" :: "l"(p), "r"(v) : "memory");
}
__device__ __forceinline__ void sts128(uint32_t addr, unsigned a, unsigned b,
                                       unsigned c, unsigned d){
  asm volatile("st.shared.v4.b32 [%0], {%1,%2,%3,%4};"
               :: "r"(addr), "r"(a), "r"(b), "r"(c), "r"(d) : "memory");
}
__device__ __forceinline__ void lds128(uint32_t addr, unsigned& a, unsigned& b,
                                       unsigned& c, unsigned& d){
  asm volatile("ld.shared.v4.b32 {%0,%1,%2,%3}, [%4];"
               : "=r"(a), "=r"(b), "=r"(c), "=r"(d) : "r"(addr));
}
__device__ __forceinline__ unsigned pack2(float a, float b){
  __half2 h = __floats2half2_rn(a, b);
  return *(unsigned*)&h;
}

// ---------------- per-layer persistent worker (EXACT R10 structure) ----------------
// INP warps (4..7) stage+GEMM the input contribution and dump it (fp16) to
// gbuf DURING REC's recurrent GEMM; REC warps (0..3) consume the dump and run
// the full gate epilogue (creg lives in REC). Aggregated per-layer release
// counter. bar1: INP arrive (dump ready) / REC sync. bar2: REC arrive (dump
// consumed) / INP sync — WAR backpressure for the next dump.
template<int DINA>
__device__ __forceinline__ void run_layer(const int l, const int cid,
                                          const float* __restrict__ c0,
                                          float* __restrict__ out, char* smem_raw)
{
  constexpr int SIW = SIWC;
  constexpr int NI  = DINA/16;               // input k16 iters
  constexpr int CHI = DINA/8;                // input 16B chunks per row
  __half* ws = (__half*)smem_raw;            // [64][520]
  __half* A  = ws + 64*SIW;                  // [128][520]
  uint32_t* gbuf = (uint32_t*)(A + 128*SIW); // 128 slots * GSTR bytes
  const int tid = threadIdx.x;

  {
    const __half* src = d_wpack + ((size_t)(l*FOURH + cid*64))*KMAX;
    for (int v = tid; v < 64*64; v += NTH){
      int r = v >> 6, kk = (v & 63)*8;
      *(uint4*)(ws + r*SIW + kk) = *(const uint4*)(src + (size_t)r*KMAX + kk);
    }
  }

  const int w = tid >> 5, lane = tid & 31;
  const int q = lane >> 3, rs = lane & 7;
  const int gid = lane >> 2, ct = lane & 3;

  unsigned bX[4];
  {
    const int Xs[4] = {0, 8, 32, 40};
    #pragma unroll
    for (int i = 0; i < 4; i++)
      bX[i] = smem_u32(ws + (Xs[i] + rs + ((q>>1)<<4))*SIW + ((q&1)<<3));
  }
  const uint32_t Abase = smem_u32(A);

  __syncthreads();

  if (w < 4){
    // ========== REC warps: critical path + epilogue ==========
    const unsigned aB0 = smem_u32(A + (w*32 + rs + ((q&1)<<3))*SIW + ((q>>1)<<3));
    const unsigned aB1 = aB0 + (unsigned)(32*SIW);
    const uint32_t gsrc = smem_u32(gbuf) + (unsigned)tid*GSTR;

    float bias[16];
    #pragma unroll
    for (int g = 0; g < 4; g++)
      #pragma unroll
      for (int jh = 0; jh < 2; jh++)
        #pragma unroll
        for (int cc = 0; cc < 2; cc++)
          bias[g*4 + jh*2 + cc] = d_bpack[l*FOURH + cid*64 + g*16 + jh*8 + ct*2 + cc];

    float creg[16];
    #pragma unroll
    for (int mt = 0; mt < 2; mt++)
      #pragma unroll
      for (int rr = 0; rr < 2; rr++)
        #pragma unroll
        for (int jh = 0; jh < 2; jh++)
          #pragma unroll
          for (int cc = 0; cc < 2; cc++){
            int row = w*32 + mt*16 + gid + rr*8;
            int col = cid*16 + jh*8 + ct*2 + cc;
            creg[mt*8 + rr*4 + jh*2 + cc] = c0[(l*BB + row)*HH + col];
          }

    for (int t = 0; t < TT; t++){
      if (tid == 0){
        if (t > 0)               wait_ge(&g_arrive[l],   16u*(unsigned)t);
        if (l < LL-1 && t >= 3)  wait_ge(&g_arrive[l+1], 16u*(unsigned)(t-2));
      }
      bar_sync(4, 128);

      // stage own h_{t-1} (slot t&3) into A cols [0,256), two K-half groups
      const __half* hs = d_hring + hring_off(l, t&3, 0, 0);
      for (int v = tid; v < 2048; v += 128){
        int r = v >> 4, c = (v & 15)*8;
        cp_async16(Abase + (uint32_t)(r*SIW + c)*2u, hs + r*HH + c);
      }
      asm volatile("cp.async.commit_group;");
      for (int v = tid; v < 2048; v += 128){
        int r = v >> 4, c = 128 + (v & 15)*8;
        cp_async16(Abase + (uint32_t)(r*SIW + c)*2u, hs + r*HH + c);
      }
      asm volatile("cp.async.commit_group;");

      float acc[2][8][4];
      #pragma unroll
      for (int i = 0; i < 2; i++)
        #pragma unroll
        for (int j = 0; j < 8; j++)
          #pragma unroll
          for (int e = 0; e < 4; e++) acc[i][j][e] = 0.f;

      asm volatile("cp.async.wait_group 1;" ::: "memory");
      bar_sync(5, 128);
      #pragma unroll
      for (int ki = 0; ki < 8; ki++){
        const unsigned kofs = (unsigned)(ki*32);
        unsigned a0[4], a1[4], b0[4], b1[4], b2[4], b3[4];
        ldsm_x4(aB0 + kofs, a0[0], a0[1], a0[2], a0[3]);
        ldsm_x4(aB1 + kofs, a1[0], a1[1], a1[2], a1[3]);
        ldsm_x4(bX[0] + kofs, b0[0], b0[1], b0[2], b0[3]);
        ldsm_x4(bX[1] + kofs, b1[0], b1[1], b1[2], b1[3]);
        ldsm_x4(bX[2] + kofs, b2[0], b2[1], b2[2], b2[3]);
        ldsm_x4(bX[3] + kofs, b3[0], b3[1], b3[2], b3[3]);
        #pragma unroll
        for (int mt = 0; mt < 2; mt++){
          const unsigned* a = mt ? a1 : a0;
          mma_16816(acc[mt][0], a, b0[0], b0[1]);
          mma_16816(acc[mt][1], a, b1[0], b1[1]);
          mma_16816(acc[mt][2], a, b0[2], b0[3]);
          mma_16816(acc[mt][3], a, b1[2], b1[3]);
          mma_16816(acc[mt][4], a, b2[0], b2[1]);
          mma_16816(acc[mt][5], a, b3[0], b3[1]);
          mma_16816(acc[mt][6], a, b2[2], b2[3]);
          mma_16816(acc[mt][7], a, b3[2], b3[3]);
        }
      }
      asm volatile("cp.async.wait_group 0;" ::: "memory");
      bar_sync(4, 128);
      #pragma unroll
      for (int ki = 8; ki < 16; ki++){
        const unsigned kofs = (unsigned)(ki*32);
        unsigned a0[4], a1[4], b0[4], b1[4], b2[4], b3[4];
        ldsm_x4(aB0 + kofs, a0[0], a0[1], a0[2], a0[3]);
        ldsm_x4(aB1 + kofs, a1[0], a1[1], a1[2], a1[3]);
        ldsm_x4(bX[0] + kofs, b0[0], b0[1], b0[2], b0[3]);
        ldsm_x4(bX[1] + kofs, b1[0], b1[1], b1[2], b1[3]);
        ldsm_x4(bX[2] + kofs, b2[0], b2[1], b2[2], b2[3]);
        ldsm_x4(bX[3] + kofs, b3[0], b3[1], b3[2], b3[3]);
        #pragma unroll
        for (int mt = 0; mt < 2; mt++){
          const unsigned* a = mt ? a1 : a0;
          mma_16816(acc[mt][0], a, b0[0], b0[1]);
          mma_16816(acc[mt][1], a, b1[0], b1[1]);
          mma_16816(acc[mt][2], a, b0[2], b0[3]);
          mma_16816(acc[mt][3], a, b1[2], b1[3]);
          mma_16816(acc[mt][4], a, b2[0], b2[1]);
          mma_16816(acc[mt][5], a, b3[0], b3[1]);
          mma_16816(acc[mt][6], a, b2[2], b2[3]);
          mma_16816(acc[mt][7], a, b3[2], b3[3]);
        }
      }

      // consume INP dump (posted during our GEMM)
      bar_sync(1, NTH);
      unsigned g32[32];
      #pragma unroll
      for (int i = 0; i < 8; i++)
        lds128(gsrc + (unsigned)(i*16), g32[4*i], g32[4*i+1], g32[4*i+2], g32[4*i+3]);
      bar_arrive(2, NTH);

      // epilogue: gates = acc (recurrent fp32) + g32 (input fp16) + bias
      __half* hslot = d_hring + hring_off(l, (t+1)&3, 0, 0);
      #pragma unroll
      for (int mt = 0; mt < 2; mt++)
        #pragma unroll
        for (int rr = 0; rr < 2; rr++){
          int row = w*32 + mt*16 + gid + rr*8;
          #pragma unroll
          for (int jh = 0; jh < 2; jh++){
            float2 gI = __half22float2(*(const __half2*)&g32[(mt*8 +      jh)*2 + rr]);
            float2 gF = __half22float2(*(const __half2*)&g32[(mt*8 + 2 + jh)*2 + rr]);
            float2 gG = __half22float2(*(const __half2*)&g32[(mt*8 + 4 + jh)*2 + rr]);
            float2 gO = __half22float2(*(const __half2*)&g32[(mt*8 + 6 + jh)*2 + rr]);
            float hv[2];
            #pragma unroll
            for (int cc = 0; cc < 2; cc++){
              int e  = rr*2 + cc;
              int ci = mt*8 + rr*4 + jh*2 + cc;
              float gi = acc[mt][     jh][e] + (cc ? gI.y : gI.x) + bias[     jh*2 + cc];
              float gf = acc[mt][2 + jh][e] + (cc ? gF.y : gF.x) + bias[ 4 + jh*2 + cc];
              float gg = acc[mt][4 + jh][e] + (cc ? gG.y : gG.x) + bias[ 8 + jh*2 + cc];
              float go = acc[mt][6 + jh][e] + (cc ? gO.y : gO.x) + bias[12 + jh*2 + cc];
              float c  = sig_fast(gf)*creg[ci] + sig_fast(gi)*tanh_fast(gg);
              creg[ci] = c;
              hv[cc]   = sig_fast(go)*tanh_fast(c);
            }
            int col0 = cid*16 + jh*8 + ct*2;
            st_cg_u32(hslot + row*HH + col0, pack2(hv[0], hv[1]));
            if (t == TT-1){
              out[(l*BB + row)*HH + col0    ] = hv[0];
              out[(l*BB + row)*HH + col0 + 1] = hv[1];
            }
          }
        }
      bar_sync(4, 128);
      if (tid == 0) arrive_release(&g_arrive[l]);
    }
  } else {
    // ========== INP warps: input stage + GEMM + dump (off critical path) ==========
    const int wi = w - 4;
    const unsigned aI0 = smem_u32(A + (wi*32 + rs + ((q&1)<<3))*SIW + 256 + ((q>>1)<<3));
    const unsigned aI1 = aI0 + (unsigned)(32*SIW);
    unsigned bI[4];
    #pragma unroll
    for (int i = 0; i < 4; i++) bI[i] = bX[i] + 512u;
    const uint32_t gdst = smem_u32(gbuf) + (unsigned)(tid - 128)*GSTR;

    auto stage_input = [&](int tt){
      for (int v = tid - 128; v < 128*CHI; v += 128){
        int r = v / CHI, kk = (v - r*CHI)*8;
        const __half* src = (DINA == INW)
          ? d_xh + ((size_t)r*TT + tt)*INW + kk
          : d_hring + hring_off(l-1, (tt+1)&3, r, kk);
        cp_async16(Abase + (uint32_t)(r*SIW + 256 + kk)*2u, src);
      }
      asm volatile("cp.async.commit_group;");
      asm volatile("cp.async.wait_group 0;" ::: "memory");
    };

    if (tid == 128 && l > 0) wait_ge(&g_arrive[l-1], 16u);
    bar_sync(3, 128);
    stage_input(0);
    bar_sync(3, 128);

    for (int t = 0; t < TT; t++){
      float accI[2][8][4];
      #pragma unroll
      for (int i = 0; i < 2; i++)
        #pragma unroll
        for (int j = 0; j < 8; j++)
          #pragma unroll
          for (int e = 0; e < 4; e++) accI[i][j][e] = 0.f;
      #pragma unroll
      for (int ki = 0; ki < NI; ki++){
        const unsigned kofs = (unsigned)(ki*32);
        unsigned a0[4], a1[4], b0[4], b1[4], b2[4], b3[4];
        ldsm_x4(aI0 + kofs, a0[0], a0[1], a0[2], a0[3]);
        ldsm_x4(aI1 + kofs, a1[0], a1[1], a1[2], a1[3]);
        ldsm_x4(bI[0] + kofs, b0[0], b0[1], b0[2], b0[3]);
        ldsm_x4(bI[1] + kofs, b1[0], b1[1], b1[2], b1[3]);
        ldsm_x4(bI[2] + kofs, b2[0], b2[1], b2[2], b2[3]);
        ldsm_x4(bI[3] + kofs, b3[0], b3[1], b3[2], b3[3]);
        #pragma unroll
        for (int mt = 0; mt < 2; mt++){
          const unsigned* a = mt ? a1 : a0;
          mma_16816(accI[mt][0], a, b0[0], b0[1]);
          mma_16816(accI[mt][1], a, b1[0], b1[1]);
          mma_16816(accI[mt][2], a, b0[2], b0[3]);
          mma_16816(accI[mt][3], a, b1[2], b1[3]);
          mma_16816(accI[mt][4], a, b2[0], b2[1]);
          mma_16816(accI[mt][5], a, b3[0], b3[1]);
          mma_16816(accI[mt][6], a, b2[2], b2[3]);
          mma_16816(accI[mt][7], a, b3[2], b3[3]);
        }
      }

      if (t > 0) bar_sync(2, NTH);     // REC consumed dump(t-1)
      #pragma unroll
      for (int i = 0; i < 8; i++){
        const int j0 = 2*i, j1 = 2*i + 1;
        const float* t0 = accI[j0 >> 3][j0 & 7];
        const float* t1 = accI[j1 >> 3][j1 & 7];
        sts128(gdst + (unsigned)(i*16),
               pack2(t0[0], t0[1]), pack2(t0[2], t0[3]),
               pack2(t1[0], t1[1]), pack2(t1[2], t1[3]));
      }
      asm volatile("membar.cta;" ::: "memory");
      bar_arrive(1, NTH);              // dump(t) ready; REC consumes

      if (t < TT-1){
        if (tid == 128 && l > 0) wait_ge(&g_arrive[l-1], 16u*(unsigned)(t+2));
        bar_sync(3, 128);
        stage_input(t+1);
        bar_sync(3, 128);
      }
    }
  }
}

__global__ void __launch_bounds__(NTH, 1)
lstm_persist(const float* __restrict__ c0, float* __restrict__ out)
{
  extern __shared__ __align__(16) char smem_raw[];
  const int l = blockIdx.x >> 4, cid = blockIdx.x & 15;
  if (l == 0) run_layer<INW>(0, cid, c0, out, smem_raw);
  else        run_layer<HH >(l, cid, c0, out, smem_raw);
}

// ---------------- launch ----------------
extern "C" void kernel_launch(void* const* d_in, const int* in_sizes, int n_in,
                              void* d_out, int out_size){
  const float* x     = (const float*)d_in[0];
  const float* h0    = (const float*)d_in[1];
  const float* c0    = (const float*)d_in[2];
  const float* w_ih0 = (const float*)d_in[3];
  const float* w_ih  = (const float*)d_in[4];
  const float* w_hh  = (const float*)d_in[5];
  const float* b_ih  = (const float*)d_in[6];
  const float* b_hh  = (const float*)d_in[7];
  float* out = (float*)d_out;

  cudaFuncSetAttribute(lstm_persist, cudaFuncAttributeMaxDynamicSharedMemorySize, SMEM_BYTES);

  prep_pack<<<(LL*FOURH*(KMAX/8) + 255)/256, 256>>>(w_ih0, w_ih, w_hh, b_ih, b_hh);
  prep_x   <<<(BB*TT*INW/8      + 255)/256, 256>>>(x);
  prep_init<<<(LL*BB*HH         + 255)/256, 256>>>(h0);
  lstm_persist<<<GRIDB, NTH, SMEM_BYTES>>>(c0, out);
}